// round 2
// baseline (speedup 1.0000x reference)
#include <cuda_runtime.h>
#include <mma.h>
#include <cstdint>

using namespace nvcuda;

#define BM 128
#define BN 128
#define BK 32
#define WM 64
#define WN 32
#define THREADS 256

// ---------------- scratch (device globals; no allocation allowed) ----------
__device__ float g_G [64L * 512 * 512];
__device__ float g_M1[64L * 512 * 512];
__device__ float g_L [64L * 512 * 512];
__device__ float g_W [64L * 512 * 512];

// ---------------- cp.async helpers ----------------------------------------
__device__ __forceinline__ void cpa16(float* s, const float* g) {
    uint32_t sa = (uint32_t)__cvta_generic_to_shared(s);
    asm volatile("cp.async.cg.shared.global [%0], [%1], 16;\n" :: "r"(sa), "l"(g));
}
#define CP_COMMIT()  asm volatile("cp.async.commit_group;\n" ::: "memory")
#define CP_WAIT(n)   asm volatile("cp.async.wait_group %0;\n" :: "n"(n) : "memory")

__device__ __forceinline__ float hi_split(float v) {
    return __int_as_float(__float_as_int(v) & 0xffffe000);
}

template<bool TA> struct ASel            { using type = wmma::row_major; };
template<>        struct ASel<true>      { using type = wmma::col_major; };

// ---------------- generic batched tf32x3 GEMM -------------------------------
// C[bz] = op(A[bz % aMod]) * B[bz % bMod], fp32-accurate via hi/lo split:
//   C = Ah*Bh + Ah*Bl + Al*Bh   (lo*lo term negligible)
template<bool TA>
__global__ void __launch_bounds__(THREADS)
gemm_tf32_kernel(const float* __restrict__ A, const float* __restrict__ B,
                 float* __restrict__ C,
                 int K, int lda, int ldb, int ldc,
                 long aStride, long bStride, long cStride,
                 int aMod, int bMod)
{
    extern __shared__ float smem[];
    constexpr int AS = TA ? BK * (BM + 8) : BM * (BK + 8);
    constexpr int BS = BK * (BN + 8);

    const int bz = blockIdx.z;
    const float* Ab = A + (size_t)(bz % aMod) * aStride;
    const float* Bb = B + (size_t)(bz % bMod) * bStride;
    float*       Cb = C + (size_t)bz * cStride;

    const int m0 = blockIdx.y * BM;
    const int n0 = blockIdx.x * BN;
    const int tid = threadIdx.x;
    const int wid = tid >> 5;
    const int wm  = wid & 1;   // 2 warps along M
    const int wn  = wid >> 1;  // 4 warps along N

    float* AsP[2] = { smem,            smem + AS + BS };
    float* BsP[2] = { smem + AS,       smem + AS + BS + AS };

    wmma::fragment<wmma::accumulator, 16, 16, 8, float> acc[4][2];
    #pragma unroll
    for (int mi = 0; mi < 4; mi++)
        #pragma unroll
        for (int ni = 0; ni < 2; ni++)
            wmma::fill_fragment(acc[mi][ni], 0.0f);

    auto loadA = [&](int t, float* as) {
        const int k0 = t * BK;
        #pragma unroll
        for (int i = 0; i < 4; i++) {
            int idx = tid + i * THREADS;
            if (TA) {
                int k = idx >> 5, m4 = (idx & 31) * 4;
                cpa16(as + k * (BM + 8) + m4,
                      Ab + (size_t)(k0 + k) * lda + m0 + m4);
            } else {
                int m = idx >> 3, k4 = (idx & 7) * 4;
                cpa16(as + m * (BK + 8) + k4,
                      Ab + (size_t)(m0 + m) * lda + k0 + k4);
            }
        }
    };
    auto loadB = [&](int t, float* bs) {
        const int k0 = t * BK;
        #pragma unroll
        for (int i = 0; i < 4; i++) {
            int idx = tid + i * THREADS;
            int k = idx >> 5, n4 = (idx & 31) * 4;
            cpa16(bs + k * (BN + 8) + n4,
                  Bb + (size_t)(k0 + k) * ldb + n0 + n4);
        }
    };

    const int T = K / BK;
    loadA(0, AsP[0]);
    loadB(0, BsP[0]);
    CP_COMMIT();

    for (int t = 0; t < T; t++) {
        if (t + 1 < T) {
            loadA(t + 1, AsP[(t + 1) & 1]);
            loadB(t + 1, BsP[(t + 1) & 1]);
            CP_COMMIT();
            CP_WAIT(1);
        } else {
            CP_WAIT(0);
        }
        __syncthreads();

        const float* as = AsP[t & 1];
        const float* bs = BsP[t & 1];

        #pragma unroll
        for (int kk = 0; kk < BK / 8; kk++) {
            wmma::fragment<wmma::matrix_a, 16, 16, 8, wmma::precision::tf32,
                           typename ASel<TA>::type> ah[4], al[4];
            wmma::fragment<wmma::matrix_b, 16, 16, 8, wmma::precision::tf32,
                           wmma::row_major> bh[2], bl[2];
            #pragma unroll
            for (int mi = 0; mi < 4; mi++) {
                const float* p = TA
                    ? (as + (kk * 8) * (BM + 8) + wm * WM + mi * 16)
                    : (as + (wm * WM + mi * 16) * (BK + 8) + kk * 8);
                wmma::load_matrix_sync(ah[mi], p, TA ? (BM + 8) : (BK + 8));
                #pragma unroll
                for (int e = 0; e < ah[mi].num_elements; e++) {
                    float v = ah[mi].x[e], h = hi_split(v);
                    ah[mi].x[e] = h;
                    al[mi].x[e] = v - h;
                }
            }
            #pragma unroll
            for (int ni = 0; ni < 2; ni++) {
                const float* p = bs + (kk * 8) * (BN + 8) + wn * WN + ni * 16;
                wmma::load_matrix_sync(bh[ni], p, BN + 8);
                #pragma unroll
                for (int e = 0; e < bh[ni].num_elements; e++) {
                    float v = bh[ni].x[e], h = hi_split(v);
                    bh[ni].x[e] = h;
                    bl[ni].x[e] = v - h;
                }
            }
            #pragma unroll
            for (int mi = 0; mi < 4; mi++)
                #pragma unroll
                for (int ni = 0; ni < 2; ni++) {
                    wmma::mma_sync(acc[mi][ni], ah[mi], bl[ni], acc[mi][ni]);
                    wmma::mma_sync(acc[mi][ni], al[mi], bh[ni], acc[mi][ni]);
                    wmma::mma_sync(acc[mi][ni], ah[mi], bh[ni], acc[mi][ni]);
                }
        }
        __syncthreads();
    }

    #pragma unroll
    for (int mi = 0; mi < 4; mi++)
        #pragma unroll
        for (int ni = 0; ni < 2; ni++)
            wmma::store_matrix_sync(
                Cb + (size_t)(m0 + wm * WM + mi * 16) * ldc + n0 + wn * WN + ni * 16,
                acc[mi][ni], ldc, wmma::mem_row_major);
}

// ---------------- row softmax over 512 columns ------------------------------
__global__ void softmax512_kernel(float* __restrict__ L) {
    const int row = blockIdx.x;
    float4* p = reinterpret_cast<float4*>(L + (size_t)row * 512);
    float4 v = p[threadIdx.x];

    const int lane = threadIdx.x & 31;
    const int warp = threadIdx.x >> 5;
    __shared__ float smax[4], ssum[4];

    float m = fmaxf(fmaxf(v.x, v.y), fmaxf(v.z, v.w));
    #pragma unroll
    for (int o = 16; o > 0; o >>= 1) m = fmaxf(m, __shfl_xor_sync(0xffffffffu, m, o));
    if (lane == 0) smax[warp] = m;
    __syncthreads();
    m = fmaxf(fmaxf(smax[0], smax[1]), fmaxf(smax[2], smax[3]));

    v.x = __expf(v.x - m); v.y = __expf(v.y - m);
    v.z = __expf(v.z - m); v.w = __expf(v.w - m);

    float s = v.x + v.y + v.z + v.w;
    #pragma unroll
    for (int o = 16; o > 0; o >>= 1) s += __shfl_xor_sync(0xffffffffu, s, o);
    if (lane == 0) ssum[warp] = s;
    __syncthreads();
    s = ssum[0] + ssum[1] + ssum[2] + ssum[3];

    const float inv = 1.0f / s;
    v.x *= inv; v.y *= inv; v.z *= inv; v.w *= inv;
    p[threadIdx.x] = v;
}

// ---------------- launch ----------------------------------------------------
extern "C" void kernel_launch(void* const* d_in, const int* in_sizes, int n_in,
                              void* d_out, int out_size)
{
    const float* x  = (const float*)d_in[0];  // [4,16,1024,512]
    const float* w1 = (const float*)d_in[1];  // [16,512,512]
    const float* w2 = (const float*)d_in[2];
    const float* w3 = (const float*)d_in[3];
    float* out = (float*)d_out;               // [4,16,1024,512]

    float *G, *M1, *L, *W;
    cudaGetSymbolAddress((void**)&G,  g_G);
    cudaGetSymbolAddress((void**)&M1, g_M1);
    cudaGetSymbolAddress((void**)&L,  g_L);
    cudaGetSymbolAddress((void**)&W,  g_W);

    const size_t smemTA = 2 * (size_t)(BK * (BM + 8) + BK * (BN + 8)) * 4; // 69632
    const size_t smemNA = 2 * (size_t)(BM * (BK + 8) + BK * (BN + 8)) * 4; // 75776
    cudaFuncSetAttribute(gemm_tf32_kernel<true>,
                         cudaFuncAttributeMaxDynamicSharedMemorySize, (int)smemTA);
    cudaFuncSetAttribute(gemm_tf32_kernel<false>,
                         cudaFuncAttributeMaxDynamicSharedMemorySize, (int)smemNA);

    const long sX = 1024L * 512;   // per-(b,e) x stride
    const long sD = 512L * 512;    // per-(b,e) 512x512 stride

    dim3 blk(THREADS);
    dim3 grd512(512 / BN, 512 / BM, 64);
    dim3 grdOut(512 / BN, 1024 / BM, 64);

    // 1) G = x^T x        (M=N=512, K=1024)
    gemm_tf32_kernel<true ><<<grd512, blk, smemTA>>>(x,  x,  G,  1024, 512, 512, 512, sX, sX, sD, 64, 64);
    // 2) M1 = G * w2      (K=512)
    gemm_tf32_kernel<false><<<grd512, blk, smemNA>>>(G,  w2, M1,  512, 512, 512, 512, sD, sD, sD, 64, 16);
    // 3) L = w1^T * M1
    gemm_tf32_kernel<true ><<<grd512, blk, smemTA>>>(w1, M1, L,   512, 512, 512, 512, sD, sD, sD, 16, 64);
    // 4) A = softmax_rows(L)
    softmax512_kernel<<<64 * 512, 128>>>(L);
    // 5) W = w3 * A
    gemm_tf32_kernel<false><<<grd512, blk, smemNA>>>(w3, L,  W,   512, 512, 512, 512, sD, sD, sD, 16, 64);
    // 6) out = x * W      (M=1024, K=512)
    gemm_tf32_kernel<false><<<grdOut, blk, smemNA>>>(x,  W,  out, 512, 512, 512, 512, sX, sD, sX, 64, 64);
}

// round 5
// speedup vs baseline: 2.1186x; 2.1186x over previous
#include <cuda_runtime.h>
#include <cuda_bf16.h>
#include <mma.h>
#include <cstdint>

using namespace nvcuda;
typedef __nv_bfloat16 bf16;

// ===================== scratch (device globals) =============================
#define NBZ 64
__device__ bf16 g_xT_h[(size_t)NBZ * 512 * 1024];
__device__ bf16 g_xT_l[(size_t)NBZ * 512 * 1024];
__device__ bf16 g_x_h [(size_t)NBZ * 1024 * 512];
__device__ bf16 g_x_l [(size_t)NBZ * 1024 * 512];
__device__ bf16 g_w1T_h[(size_t)16 * 512 * 512];
__device__ bf16 g_w1T_l[(size_t)16 * 512 * 512];
__device__ bf16 g_w2T_h[(size_t)16 * 512 * 512];
__device__ bf16 g_w2T_l[(size_t)16 * 512 * 512];
__device__ bf16 g_w3_h [(size_t)16 * 512 * 512];
__device__ bf16 g_w3_l [(size_t)16 * 512 * 512];
__device__ bf16 g_G_h [(size_t)NBZ * 512 * 512];
__device__ bf16 g_G_l [(size_t)NBZ * 512 * 512];
__device__ bf16 g_M2_h[(size_t)NBZ * 512 * 512];
__device__ bf16 g_M2_l[(size_t)NBZ * 512 * 512];
__device__ bf16 g_AsT_h[(size_t)NBZ * 512 * 512];
__device__ bf16 g_AsT_l[(size_t)NBZ * 512 * 512];
__device__ bf16 g_WT_h[(size_t)NBZ * 512 * 512];
__device__ bf16 g_WT_l[(size_t)NBZ * 512 * 512];
__device__ float g_Gf [(size_t)NBZ * 512 * 512];
__device__ float g_M2f[(size_t)NBZ * 512 * 512];
__device__ float g_L  [(size_t)NBZ * 512 * 512];
__device__ float g_WTf[(size_t)NBZ * 512 * 512];

// ===================== helpers =============================================
__device__ __forceinline__ uint32_t smem_u32(const void* p) {
    uint32_t a;
    asm("{ .reg .u64 t; cvta.to.shared.u64 t, %1; cvt.u32.u64 %0, t; }"
        : "=r"(a) : "l"(p));
    return a;
}
__device__ __forceinline__ void cpa16(uint32_t s, const void* g) {
    asm volatile("cp.async.cg.shared.global [%0], [%1], 16;\n" :: "r"(s), "l"(g));
}
#define CPA_COMMIT() asm volatile("cp.async.commit_group;\n" ::: "memory")

__device__ __forceinline__ void split2(float a, float b, uint32_t& hp, uint32_t& lp) {
    bf16 ha = __float2bfloat16_rn(a), hb = __float2bfloat16_rn(b);
    bf16 la = __float2bfloat16_rn(a - __bfloat162float(ha));
    bf16 lb = __float2bfloat16_rn(b - __bfloat162float(hb));
    hp = ((uint32_t)__bfloat16_as_ushort(hb) << 16) | __bfloat16_as_ushort(ha);
    lp = ((uint32_t)__bfloat16_as_ushort(lb) << 16) | __bfloat16_as_ushort(la);
}

// ===================== prepass: split (+ optional transpose) ================
// in: [bz][R][C] f32.  STRAIGHT -> sh/sl [bz][R][C].  TRANS -> th/tl [bz][C][R].
template<bool STRAIGHT, bool TRANS>
__global__ void split_kernel(const float* __restrict__ in,
                             bf16* __restrict__ sh, bf16* __restrict__ sl,
                             bf16* __restrict__ th, bf16* __restrict__ tl,
                             int R, int C)
{
    __shared__ float tile[32][33];
    const int bz = blockIdx.z;
    const float* ib = in + (size_t)bz * R * C;
    const int c0 = blockIdx.x * 32, r0 = blockIdx.y * 32;
    const int tx = threadIdx.x, ty = threadIdx.y;  // 16 x 16

    #pragma unroll
    for (int ry = 0; ry < 2; ry++) {
        int r = ty * 2 + ry;
        float2 v = *(const float2*)(ib + (size_t)(r0 + r) * C + c0 + tx * 2);
        if (TRANS) { tile[tx * 2][r] = v.x; tile[tx * 2 + 1][r] = v.y; }
        if (STRAIGHT) {
            uint32_t hp, lp; split2(v.x, v.y, hp, lp);
            size_t o = ((size_t)bz * R * C + (size_t)(r0 + r) * C + c0 + tx * 2) >> 1;
            ((uint32_t*)sh)[o] = hp; ((uint32_t*)sl)[o] = lp;
        }
    }
    if (TRANS) {
        __syncthreads();
        #pragma unroll
        for (int cy = 0; cy < 2; cy++) {
            int c = ty * 2 + cy;
            float a = tile[c][tx * 2], b = tile[c][tx * 2 + 1];
            uint32_t hp, lp; split2(a, b, hp, lp);
            size_t o = ((size_t)bz * C * R + (size_t)(c0 + c) * R + r0 + tx * 2) >> 1;
            ((uint32_t*)th)[o] = hp; ((uint32_t*)tl)[o] = lp;
        }
    }
}

// ===================== bf16x3 GEMM via wmma (HMMA) ==========================
// C[bz][m][n] = sum_k A[m,k]*B[n,k]; A,B given as bf16 hi/lo pairs, K-major.
// M = gridDim.y*128, N = gridDim.x*128, ldc = Nt.  K multiple of 32.
#define LDS 40                       // smem row stride in bf16 (80B, LDSM conflict-free)
#define TILE_E (128 * LDS)           // elements per operand tile
#define STAGE_E (4 * TILE_E)         // Ah Al Bh Bl
#define GEMM_SMEM (2 * STAGE_E * 2)  // bytes, 2 stages  (81920)

__global__ void __launch_bounds__(256, 1)
gemm_bf16x3(const bf16* __restrict__ Ah, const bf16* __restrict__ Al,
            const bf16* __restrict__ Bh, const bf16* __restrict__ Bl,
            float* __restrict__ C, int K, int Nt, int aMod, int bMod)
{
    extern __shared__ bf16 smem[];
    const int tid = threadIdx.x;
    const int wid = tid >> 5;
    const int wm  = wid & 1;    // 2 warps along M (64 rows each)
    const int wn  = wid >> 1;   // 4 warps along N (32 cols each)
    const int bz = blockIdx.z;
    const int M = gridDim.y * 128;

    const size_t aOff = (size_t)(bz % aMod) * M * K + (size_t)blockIdx.y * 128 * K;
    const size_t bOff = (size_t)(bz % bMod) * Nt * K + (size_t)blockIdx.x * 128 * K;
    const bf16* gp[4] = { Ah + aOff, Al + aOff, Bh + bOff, Bl + bOff };

    wmma::fragment<wmma::accumulator, 16, 16, 16, float> acc[4][2];
    #pragma unroll
    for (int mi = 0; mi < 4; mi++)
        #pragma unroll
        for (int ni = 0; ni < 2; ni++)
            wmma::fill_fragment(acc[mi][ni], 0.0f);

    auto load_chunk = [&](int t, int s) {
        bf16* st = smem + s * STAGE_E;
        const int k0 = t * 32;
        #pragma unroll
        for (int i = 0; i < 8; i++) {
            int idx = tid + i * 256;            // 0..2047
            int tile = idx >> 9;
            int rem  = idx & 511;
            int r    = rem >> 2;                // 0..127
            int seg  = rem & 3;                 // 4 x 8 bf16 per row
            cpa16(smem_u32(st + tile * TILE_E + r * LDS + seg * 8),
                  gp[tile] + (size_t)r * K + k0 + seg * 8);
        }
    };

    const int T = K / 32;
    load_chunk(0, 0); CPA_COMMIT();
    load_chunk(1, 1); CPA_COMMIT();

    for (int t = 0; t < T; t++) {
        if (t + 2 < T) {
            asm volatile("cp.async.wait_group 1;" ::: "memory");
        } else {
            asm volatile("cp.async.wait_group 0;" ::: "memory");
        }
        __syncthreads();

        const bf16* aS = smem + (t & 1) * STAGE_E;
        const bf16* bS = aS + 2 * TILE_E;

        #pragma unroll
        for (int kk = 0; kk < 2; kk++) {
            wmma::fragment<wmma::matrix_a, 16, 16, 16, bf16, wmma::row_major> ah[4], al[4];
            wmma::fragment<wmma::matrix_b, 16, 16, 16, bf16, wmma::col_major> bh[2], bl[2];
            #pragma unroll
            for (int mi = 0; mi < 4; mi++) {
                const bf16* p = aS + (wm * 64 + mi * 16) * LDS + kk * 16;
                wmma::load_matrix_sync(ah[mi], p, LDS);
                wmma::load_matrix_sync(al[mi], p + TILE_E, LDS);
            }
            #pragma unroll
            for (int ni = 0; ni < 2; ni++) {
                const bf16* p = bS + (wn * 32 + ni * 16) * LDS + kk * 16;
                wmma::load_matrix_sync(bh[ni], p, LDS);
                wmma::load_matrix_sync(bl[ni], p + TILE_E, LDS);
            }
            #pragma unroll
            for (int mi = 0; mi < 4; mi++)
                #pragma unroll
                for (int ni = 0; ni < 2; ni++) {
                    wmma::mma_sync(acc[mi][ni], ah[mi], bl[ni], acc[mi][ni]);
                    wmma::mma_sync(acc[mi][ni], al[mi], bh[ni], acc[mi][ni]);
                    wmma::mma_sync(acc[mi][ni], ah[mi], bh[ni], acc[mi][ni]);
                }
        }
        __syncthreads();

        if (t + 2 < T) { load_chunk(t + 2, t & 1); CPA_COMMIT(); }
    }

    float* Cb = C + (size_t)bz * M * Nt;
    #pragma unroll
    for (int mi = 0; mi < 4; mi++)
        #pragma unroll
        for (int ni = 0; ni < 2; ni++)
            wmma::store_matrix_sync(
                Cb + (size_t)(blockIdx.y * 128 + wm * 64 + mi * 16) * Nt
                   + blockIdx.x * 128 + wn * 32 + ni * 16,
                acc[mi][ni], Nt, wmma::mem_row_major);
}

// ===================== row softmax over 512 columns =========================
__global__ void softmax512_kernel(float* __restrict__ L) {
    const int row = blockIdx.x;
    float4* p = reinterpret_cast<float4*>(L + (size_t)row * 512);
    float4 v = p[threadIdx.x];
    const int lane = threadIdx.x & 31, warp = threadIdx.x >> 5;
    __shared__ float smax[4], ssum[4];

    float m = fmaxf(fmaxf(v.x, v.y), fmaxf(v.z, v.w));
    #pragma unroll
    for (int o = 16; o > 0; o >>= 1) m = fmaxf(m, __shfl_xor_sync(~0u, m, o));
    if (lane == 0) smax[warp] = m;
    __syncthreads();
    m = fmaxf(fmaxf(smax[0], smax[1]), fmaxf(smax[2], smax[3]));

    v.x = __expf(v.x - m); v.y = __expf(v.y - m);
    v.z = __expf(v.z - m); v.w = __expf(v.w - m);
    float s = v.x + v.y + v.z + v.w;
    #pragma unroll
    for (int o = 16; o > 0; o >>= 1) s += __shfl_xor_sync(~0u, s, o);
    if (lane == 0) ssum[warp] = s;
    __syncthreads();
    s = ssum[0] + ssum[1] + ssum[2] + ssum[3];
    const float inv = 1.0f / s;
    v.x *= inv; v.y *= inv; v.z *= inv; v.w *= inv;
    p[threadIdx.x] = v;
}

// ===================== launch ===============================================
extern "C" void kernel_launch(void* const* d_in, const int* in_sizes, int n_in,
                              void* d_out, int out_size)
{
    const float* x  = (const float*)d_in[0];  // [4,16,1024,512]
    const float* w1 = (const float*)d_in[1];  // [16,512,512]
    const float* w2 = (const float*)d_in[2];
    const float* w3 = (const float*)d_in[3];
    float* out = (float*)d_out;

    bf16 *xT_h, *xT_l, *x_h, *x_l, *w1T_h, *w1T_l, *w2T_h, *w2T_l, *w3_h, *w3_l;
    bf16 *G_h, *G_l, *M2_h, *M2_l, *AsT_h, *AsT_l, *WT_h, *WT_l;
    float *Gf, *M2f, *L, *WTf;
    cudaGetSymbolAddress((void**)&xT_h, g_xT_h); cudaGetSymbolAddress((void**)&xT_l, g_xT_l);
    cudaGetSymbolAddress((void**)&x_h,  g_x_h ); cudaGetSymbolAddress((void**)&x_l,  g_x_l );
    cudaGetSymbolAddress((void**)&w1T_h, g_w1T_h); cudaGetSymbolAddress((void**)&w1T_l, g_w1T_l);
    cudaGetSymbolAddress((void**)&w2T_h, g_w2T_h); cudaGetSymbolAddress((void**)&w2T_l, g_w2T_l);
    cudaGetSymbolAddress((void**)&w3_h,  g_w3_h ); cudaGetSymbolAddress((void**)&w3_l,  g_w3_l );
    cudaGetSymbolAddress((void**)&G_h,  g_G_h ); cudaGetSymbolAddress((void**)&G_l,  g_G_l );
    cudaGetSymbolAddress((void**)&M2_h, g_M2_h); cudaGetSymbolAddress((void**)&M2_l, g_M2_l);
    cudaGetSymbolAddress((void**)&AsT_h, g_AsT_h); cudaGetSymbolAddress((void**)&AsT_l, g_AsT_l);
    cudaGetSymbolAddress((void**)&WT_h, g_WT_h); cudaGetSymbolAddress((void**)&WT_l, g_WT_l);
    cudaGetSymbolAddress((void**)&Gf,  g_Gf );
    cudaGetSymbolAddress((void**)&M2f, g_M2f);
    cudaGetSymbolAddress((void**)&L,   g_L  );
    cudaGetSymbolAddress((void**)&WTf, g_WTf);

    cudaFuncSetAttribute(gemm_bf16x3, cudaFuncAttributeMaxDynamicSharedMemorySize, GEMM_SMEM);

    dim3 tb(16, 16);
    dim3 blk(256);
    dim3 g512(4, 4, NBZ);   // M = N = 512
    dim3 gOut(4, 8, NBZ);   // M = 1024, N = 512
    dim3 s512(16, 16, NBZ);

    // ---- input prepasses ----
    split_kernel<true, true ><<<dim3(16, 32, NBZ), tb>>>(x, x_h, x_l, xT_h, xT_l, 1024, 512);
    split_kernel<false, true><<<dim3(16, 16, 16), tb>>>(w1, nullptr, nullptr, w1T_h, w1T_l, 512, 512);
    split_kernel<false, true><<<dim3(16, 16, 16), tb>>>(w2, nullptr, nullptr, w2T_h, w2T_l, 512, 512);
    split_kernel<true, false><<<dim3(16, 16, 16), tb>>>(w3, w3_h, w3_l, nullptr, nullptr, 512, 512);

    // ---- chain (all GEMMs: C[m][n] = sum_k A[m,k] B[n,k]) ----
    // G[d1][d2] = sum_n xT[d1,n] xT[d2,n]   (K=1024); G symmetric
    gemm_bf16x3<<<g512, blk, GEMM_SMEM>>>(xT_h, xT_l, xT_h, xT_l, Gf, 1024, 512, NBZ, NBZ);
    split_kernel<true, false><<<s512, tb>>>(Gf, G_h, G_l, nullptr, nullptr, 512, 512);
    // M2[d'][a] = sum_b w2T[d',b] G[a,b]    (K=512)   ( = (G w2)^T via symmetry )
    gemm_bf16x3<<<g512, blk, GEMM_SMEM>>>(w2T_h, w2T_l, G_h, G_l, M2f, 512, 512, 16, NBZ);
    split_kernel<true, false><<<s512, tb>>>(M2f, M2_h, M2_l, nullptr, nullptr, 512, 512);
    // L[h][d'] = sum_a w1T[h,a] M2[d',a]    (K=512)
    gemm_bf16x3<<<g512, blk, GEMM_SMEM>>>(w1T_h, w1T_l, M2_h, M2_l, L, 512, 512, 16, NBZ);
    // softmax over d' (rows), then transpose-split to AsT[d'][h]
    softmax512_kernel<<<NBZ * 512, 128>>>(L);
    split_kernel<false, true><<<s512, tb>>>(L, nullptr, nullptr, AsT_h, AsT_l, 512, 512);
    // WT[d][c] = sum_h AsT[d,h] w3[c,h]     (K=512)
    gemm_bf16x3<<<g512, blk, GEMM_SMEM>>>(AsT_h, AsT_l, w3_h, w3_l, WTf, 512, 512, NBZ, 16);
    split_kernel<true, false><<<s512, tb>>>(WTf, WT_h, WT_l, nullptr, nullptr, 512, 512);
    // out[n][d] = sum_c x[n,c] WT[d,c]      (K=512, M=1024)
    gemm_bf16x3<<<gOut, blk, GEMM_SMEM>>>(x_h, x_l, WT_h, WT_l, out, 512, 512, NBZ, NBZ);
}